// round 4
// baseline (speedup 1.0000x reference)
#include <cuda_runtime.h>

#define HIDDEN   64
#define THREE_H  192
#define NTHREADS 384            // 12 warps: each thread = one half-row, BOTH batches

// named barrier ids
#define B1A 1   // batch-A dot partials ready
#define B1B 2   // batch-B dot partials ready
#define B2A 3   // batch-A h_new ready
#define B2B 4   // batch-B h_new ready

// ---------- packed f32x2 helpers ----------
__device__ __forceinline__ unsigned long long ffma2(unsigned long long a,
                                                    unsigned long long b,
                                                    unsigned long long c) {
    unsigned long long d;
    asm("fma.rn.f32x2 %0, %1, %2, %3;" : "=l"(d) : "l"(a), "l"(b), "l"(c));
    return d;
}
__device__ __forceinline__ unsigned long long fadd2(unsigned long long a,
                                                    unsigned long long b) {
    unsigned long long d;
    asm("add.rn.f32x2 %0, %1, %2;" : "=l"(d) : "l"(a), "l"(b));
    return d;
}
__device__ __forceinline__ unsigned long long pack2(float lo, float hi) {
    unsigned long long r;
    asm("mov.b64 %0, {%1, %2};" : "=l"(r) : "f"(lo), "f"(hi));
    return r;
}
__device__ __forceinline__ float2 unpack2(unsigned long long v) {
    float2 r;
    asm("mov.b64 {%0, %1}, %2;" : "=f"(r.x), "=f"(r.y) : "l"(v));
    return r;
}

// ---------- nonlinearity ----------
__device__ __forceinline__ float tanh_approx(float x) {
    float r; asm("tanh.approx.f32 %0, %1;" : "=f"(r) : "f"(x)); return r;
}
__device__ __forceinline__ float fast_rcp(float x) {
    float r; asm("rcp.approx.f32 %0, %1;" : "=f"(r) : "f"(x)); return r;
}
__device__ __forceinline__ float fast_ex2(float x) {
    float r; asm("ex2.approx.f32 %0, %1;" : "=f"(r) : "f"(x)); return r;
}
__device__ __forceinline__ float tanh_accurate(float a) {   // n-gate: protect rel_err
    a = fmaxf(a, -15.0f);
    float e = fast_ex2(a * -2.885390081777927f);            // exp(-2a)
    return (1.0f - e) * fast_rcp(1.0f + e);
}

// ---------- split named barriers ----------
__device__ __forceinline__ void bar_arrive(int id) {
    asm volatile("bar.arrive %0, %1;" :: "r"(id), "r"(NTHREADS) : "memory");
}
__device__ __forceinline__ void bar_wait(int id) {
    asm volatile("bar.sync %0, %1;" :: "r"(id), "r"(NTHREADS) : "memory");
}

__global__ void __launch_bounds__(NTHREADS, 1)
gru_scan_kernel(const float* __restrict__ x,
                const float* __restrict__ W_ih,
                const float* __restrict__ W_hh,
                const float* __restrict__ b_ih,
                const float* __restrict__ b_hh,
                const float* __restrict__ W_fc,
                const float* __restrict__ b_fc,
                float* __restrict__ out,
                int Btotal, int T)
{
    __shared__ __align__(16) float h_sh[2][HIDDEN];        // [batch][j]
    __shared__ unsigned long long psum[2][3][2][HIDDEN];   // [batch][gtype][half][j] f32x2
    __shared__ float red_sh[2][2];

    const int tid   = threadIdx.x;
    const int half  = tid / THREE_H;     // k-half: 0 -> k[0:32), 1 -> k[32:64)
    const int g     = tid % THREE_H;     // gate row
    const int gtype = g / HIDDEN;        // 0=r, 1=z, 2=n
    const int j     = g % HIDDEN;
    const int bA    = blockIdx.x * 2;
    const int bB    = bA + 1;

    const bool is_combA = (gtype == 2) && (half == 0);   // warps 4,5
    const bool is_combB = (gtype == 2) && (half == 1);   // warps 10,11
    const bool is_comb  = is_combA || is_combB;

    // ---- half-row of W_hh: 16 packed f32x2 ----
    unsigned long long w[16];
    {
        const float4* row = reinterpret_cast<const float4*>(W_hh + g * HIDDEN + half * 32);
        #pragma unroll
        for (int i = 0; i < 8; i++) {
            float4 v = row[i];
            w[2 * i]     = pack2(v.x, v.y);
            w[2 * i + 1] = pack2(v.z, v.w);
        }
    }

    // combine-thread constants (each combiner owns ONE batch)
    float wr = 0.f, wz = 0.f, wn = 0.f, br = 0.f, bz = 0.f;
    float bihn = 0.f, bhhn = 0.f, wfc = 0.f, bfc = 0.f;
    float h_old = 0.0f, xv = 0.0f;
    const float* xb = nullptr;
    if (is_comb) {
        int myb = is_combA ? bA : bB;
        if (myb >= Btotal) myb = 0;       // clamp (loads only; store guarded)
        xb   = x + (size_t)myb * T;
        wr   = W_ih[j];
        wz   = W_ih[HIDDEN + j];
        wn   = W_ih[2 * HIDDEN + j];
        br   = b_ih[j]          + b_hh[j];
        bz   = b_ih[HIDDEN + j] + b_hh[HIDDEN + j];
        bihn = b_ih[2 * HIDDEN + j];
        bhhn = b_hh[2 * HIDDEN + j];
        wfc  = W_fc[j];
        bfc  = __ldg(b_fc);
        xv   = __ldg(xb);
        h_sh[is_combA ? 0 : 1][j] = 0.0f;
    }
    __syncthreads();

    const ulonglong2* hA = reinterpret_cast<const ulonglong2*>(h_sh[0] + half * 32);
    const ulonglong2* hB = reinterpret_cast<const ulonglong2*>(h_sh[1] + half * 32);
    unsigned long long* slotA = &psum[0][gtype][half][j];
    unsigned long long* slotB = &psum[1][gtype][half][j];
    const int mslot = is_combA ? 0 : 1;

    for (int t = 0; t < T; t++) {
        // off-critical precompute for combiners
        float xnext = 0.f, irh = 0.f, izh = 0.f, i_n = 0.f;
        if (is_comb) {
            int tn = (t + 1 < T) ? t + 1 : T - 1;
            xnext = __ldg(xb + tn);
            irh = 0.5f * fmaf(xv, wr, br);    // pre-halved sigmoid args
            izh = 0.5f * fmaf(xv, wz, bz);
            i_n = fmaf(xv, wn, bihn);
        }

        // ---- dot for batch A (8 LDS.128 + 16 FFMA2, 4 chains) ----
        unsigned long long nlocal;   // combiner keeps own n-partial in a reg
        {
            unsigned long long a0, a1, a2, a3;
            ulonglong2 v0 = hA[0], v1 = hA[1];
            a0 = ffma2(w[0], v0.x, 0ull);
            a1 = ffma2(w[1], v0.y, 0ull);
            a2 = ffma2(w[2], v1.x, 0ull);
            a3 = ffma2(w[3], v1.y, 0ull);
            #pragma unroll
            for (int i = 1; i < 4; i++) {
                ulonglong2 u0 = hA[2 * i], u1 = hA[2 * i + 1];
                a0 = ffma2(w[4 * i],     u0.x, a0);
                a1 = ffma2(w[4 * i + 1], u0.y, a1);
                a2 = ffma2(w[4 * i + 2], u1.x, a2);
                a3 = ffma2(w[4 * i + 3], u1.y, a3);
            }
            unsigned long long s = fadd2(fadd2(a0, a1), fadd2(a2, a3));
            nlocal = s;
            *slotA = s;                      // STS.64 (packed)
        }
        if (!is_combA) bar_arrive(B1A);      // A-dots published

        // ---- dot for batch B ----
        {
            unsigned long long a0, a1, a2, a3;
            ulonglong2 v0 = hB[0], v1 = hB[1];
            a0 = ffma2(w[0], v0.x, 0ull);
            a1 = ffma2(w[1], v0.y, 0ull);
            a2 = ffma2(w[2], v1.x, 0ull);
            a3 = ffma2(w[3], v1.y, 0ull);
            #pragma unroll
            for (int i = 1; i < 4; i++) {
                ulonglong2 u0 = hB[2 * i], u1 = hB[2 * i + 1];
                a0 = ffma2(w[4 * i],     u0.x, a0);
                a1 = ffma2(w[4 * i + 1], u0.y, a1);
                a2 = ffma2(w[4 * i + 2], u1.x, a2);
                a3 = ffma2(w[4 * i + 3], u1.y, a3);
            }
            unsigned long long s = fadd2(fadd2(a0, a1), fadd2(a2, a3));
            if (is_combB) nlocal = s;
            *slotB = s;
        }
        if (!is_combB) bar_arrive(B1B);      // B-dots published

        // ---- combine (warps 4,5 for A; 10,11 for B) ----
        if (is_comb) {
            bar_wait(is_combA ? B1A : B1B);
            const int other = half ^ 1;
            unsigned long long pr = fadd2(psum[mslot][0][0][j], psum[mslot][0][1][j]);
            unsigned long long pz = fadd2(psum[mslot][1][0][j], psum[mslot][1][1][j]);
            unsigned long long pn = fadd2(nlocal, psum[mslot][2][other][j]);
            float2 r2 = unpack2(pr), z2 = unpack2(pz), n2 = unpack2(pn);
            float dr = r2.x + r2.y;
            float dz = z2.x + z2.y;
            float dn = n2.x + n2.y + bhhn;

            // sigmoid(s) = 0.5*tanh(0.5 s)+0.5  (1 MUFU each)
            float r    = fmaf(0.5f, tanh_approx(fmaf(0.5f, dr, irh)), 0.5f);
            float z    = fmaf(0.5f, tanh_approx(fmaf(0.5f, dz, izh)), 0.5f);
            float nval = tanh_accurate(fmaf(r, dn, i_n));
            h_old = nval + z * (h_old - nval);          // (1-z)*n + z*h
            h_sh[mslot][j] = h_old;
            xv = xnext;
            bar_arrive(is_combA ? B2A : B2B);
        }

        // ---- consume h_new barriers (waits overlap the other batch's work) ----
        if (!is_combA) bar_wait(B2A);
        if (!is_combB) bar_wait(B2B);
    }

    // ---- epilogue: out[b] = h . W_fc + b_fc ----
    if (is_comb) {
        float v = h_old * wfc;
        #pragma unroll
        for (int o = 16; o > 0; o >>= 1)
            v += __shfl_xor_sync(0xffffffffu, v, o);
        if ((j & 31) == 0) red_sh[mslot][j >> 5] = v;
    }
    __syncthreads();
    if (is_comb && j == 0) {
        int myb = is_combA ? bA : bB;
        if (myb < Btotal)
            out[myb] = red_sh[mslot][0] + red_sh[mslot][1] + bfc;
    }
}

extern "C" void kernel_launch(void* const* d_in, const int* in_sizes, int n_in,
                              void* d_out, int out_size)
{
    const float* x    = (const float*)d_in[0];
    const float* W_ih = (const float*)d_in[1];
    const float* W_hh = (const float*)d_in[2];
    const float* b_ih = (const float*)d_in[3];
    const float* b_hh = (const float*)d_in[4];
    const float* W_fc = (const float*)d_in[5];
    const float* b_fc = (const float*)d_in[6];

    int B = out_size;                 // 256
    int T = in_sizes[0] / B;          // 3000
    int grid = (B + 1) / 2;           // 128 CTAs -> 1 per SM, 2 batches each

    gru_scan_kernel<<<grid, NTHREADS>>>(x, W_ih, W_hh, b_ih, b_hh, W_fc, b_fc,
                                        (float*)d_out, B, T);
}

// round 5
// speedup vs baseline: 1.2441x; 1.2441x over previous
#include <cuda_runtime.h>

#define HIDDEN   64
#define GROUP    192            // one batch element per 192-thread group
#define NTHREADS 384            // 2 groups per CTA

// ---------- packed f32x2 helpers ----------
__device__ __forceinline__ unsigned long long ffma2(unsigned long long a,
                                                    unsigned long long b,
                                                    unsigned long long c) {
    unsigned long long d;
    asm("fma.rn.f32x2 %0, %1, %2, %3;" : "=l"(d) : "l"(a), "l"(b), "l"(c));
    return d;
}
__device__ __forceinline__ unsigned long long fadd2(unsigned long long a,
                                                    unsigned long long b) {
    unsigned long long d;
    asm("add.rn.f32x2 %0, %1, %2;" : "=l"(d) : "l"(a), "l"(b));
    return d;
}
__device__ __forceinline__ unsigned long long pack2(float lo, float hi) {
    unsigned long long r;
    asm("mov.b64 %0, {%1, %2};" : "=l"(r) : "f"(lo), "f"(hi));
    return r;
}
__device__ __forceinline__ float2 unpack2(unsigned long long v) {
    float2 r;
    asm("mov.b64 {%0, %1}, %2;" : "=f"(r.x), "=f"(r.y) : "l"(v));
    return r;
}
__device__ __forceinline__ float tanh_approx(float x) {    // 1 MUFU
    float r; asm("tanh.approx.f32 %0, %1;" : "=f"(r) : "f"(x)); return r;
}

// split named barriers, count = GROUP (128 arrives + 64 syncs on B1; 192 syncs on B2)
__device__ __forceinline__ void bar_arrive(int id) {
    asm volatile("bar.arrive %0, %1;" :: "r"(id), "r"(GROUP) : "memory");
}
__device__ __forceinline__ void bar_wait(int id) {
    asm volatile("bar.sync %0, %1;" :: "r"(id), "r"(GROUP) : "memory");
}

__global__ void __launch_bounds__(NTHREADS, 1)
gru_scan_kernel(const float* __restrict__ x,
                const float* __restrict__ W_ih,
                const float* __restrict__ W_hh,
                const float* __restrict__ b_ih,
                const float* __restrict__ b_hh,
                const float* __restrict__ W_fc,
                const float* __restrict__ b_fc,
                float* __restrict__ out,
                int Btotal, int T)
{
    __shared__ __align__(16) float h_sh[2][HIDDEN];   // [group][j]
    __shared__ float2 rz_sh[2][HIDDEN];               // packed (tau_r, tau_z)
    __shared__ float red_sh[2][2];

    const int tid   = threadIdx.x;
    const int m     = tid / GROUP;       // group = batch slot
    const int u     = tid % GROUP;       // W_hh row
    const int gtype = u / HIDDEN;        // 0=r, 1=z, 2=n
    const int j     = u % HIDDEN;
    const int b     = blockIdx.x * 2 + m;
    const bool is_n = (gtype == 2);      // combiner threads (warps 4,5 / 10,11)

    const int B1 = 1 + m;                // dots(tau) published
    const int B2 = 3 + m;                // h_new published

    // ---- full W_hh row in registers: 32 packed f32x2 ----
    unsigned long long w[32];
    {
        const float4* row = reinterpret_cast<const float4*>(W_hh + u * HIDDEN);
        #pragma unroll
        for (int i = 0; i < 16; i++) {
            float4 v = row[i];
            w[2 * i]     = pack2(v.x, v.y);
            w[2 * i + 1] = pack2(v.z, v.w);
        }
    }

    // per-role constants
    const float* xb = x + (size_t)((b < Btotal) ? b : 0) * T;
    float wih_h = 0.f, bias_h = 0.f;          // r/z: pre-halved sigmoid terms
    float wn = 0.f, bihn = 0.f, bhhn = 0.f;   // n/combine
    float wfc = 0.f, bfc = 0.f;
    float h_old = 0.0f;
    if (!is_n) {
        wih_h  = 0.5f * W_ih[u];
        bias_h = 0.5f * (b_ih[u] + b_hh[u]);
    } else {
        wn   = W_ih[u];
        bihn = b_ih[u];
        bhhn = b_hh[u];
        wfc  = W_fc[j];
        bfc  = __ldg(b_fc);
        h_sh[m][j] = 0.0f;
    }
    float xv = __ldg(xb);
    __syncthreads();

    const ulonglong2* h2 = reinterpret_cast<const ulonglong2*>(h_sh[m]);

    for (int t = 0; t < T; t++) {
        int tn = (t + 1 < T) ? t + 1 : T - 1;
        float xnext = __ldg(xb + tn);

        // x-dependent precompute (parallel to LDS-h wait)
        float a_half = 0.f, i_n = 0.f;
        if (!is_n) a_half = fmaf(xv, wih_h, bias_h);   // (x*wih + bias)/2
        else       i_n    = fmaf(xv, wn, bihn);

        // ---- row dot: 16 LDS.128 + 32 FFMA2, 4 chains ----
        unsigned long long a0, a1, a2, a3;
        {
            ulonglong2 v0 = h2[0], v1 = h2[1];
            a0 = ffma2(w[0], v0.x, 0ull);
            a1 = ffma2(w[1], v0.y, 0ull);
            a2 = ffma2(w[2], v1.x, 0ull);
            a3 = ffma2(w[3], v1.y, 0ull);
        }
        #pragma unroll
        for (int i = 1; i < 8; i++) {
            ulonglong2 v0 = h2[2 * i], v1 = h2[2 * i + 1];
            a0 = ffma2(w[4 * i],     v0.x, a0);
            a1 = ffma2(w[4 * i + 1], v0.y, a1);
            a2 = ffma2(w[4 * i + 2], v1.x, a2);
            a3 = ffma2(w[4 * i + 3], v1.y, a3);
        }
        unsigned long long s = fadd2(fadd2(a0, a1), fadd2(a2, a3));
        float2 sp = unpack2(s);
        float dot = sp.x + sp.y;

        if (!is_n) {
            // tau = tanh((i + dot)/2);  sigmoid folded into combiner's FMAs
            float tau = tanh_approx(fmaf(0.5f, dot, a_half));
            if (gtype == 0) rz_sh[m][j].x = tau;
            else            rz_sh[m][j].y = tau;
            bar_arrive(B1);
        } else {
            float dnb   = dot + bhhn;                 // n-dot stays local
            float pre_a = fmaf(0.5f, dnb, i_n);       // i_n + 0.5*dnb
            float dnb_h = 0.5f * dnb;
            bar_wait(B1);                             // taus ready
            float2 tau = rz_sh[m][j];                 // one LDS.64
            float nval = tanh_approx(fmaf(tau.x, dnb_h, pre_a));
            float d    = h_old - nval;                // h = n + z*(h-n), z=(tau.y+1)/2
            float hnew = fmaf(tau.y, 0.5f * d, fmaf(0.5f, d, nval));
            h_old = hnew;
            h_sh[m][j] = hnew;
        }

        bar_wait(B2);   // all 192: h_new visible for next step
        xv = xnext;
    }

    // ---- out[b] = h . W_fc + b_fc (h lives in n-threads' registers) ----
    if (is_n) {
        float v = h_old * wfc;
        #pragma unroll
        for (int o = 16; o > 0; o >>= 1)
            v += __shfl_xor_sync(0xffffffffu, v, o);
        if ((j & 31) == 0) red_sh[m][j >> 5] = v;
    }
    __syncthreads();
    if (is_n && j == 0 && b < Btotal) {
        out[b] = red_sh[m][0] + red_sh[m][1] + bfc;
    }
}

extern "C" void kernel_launch(void* const* d_in, const int* in_sizes, int n_in,
                              void* d_out, int out_size)
{
    const float* x    = (const float*)d_in[0];
    const float* W_ih = (const float*)d_in[1];
    const float* W_hh = (const float*)d_in[2];
    const float* b_ih = (const float*)d_in[3];
    const float* b_hh = (const float*)d_in[4];
    const float* W_fc = (const float*)d_in[5];
    const float* b_fc = (const float*)d_in[6];

    int B = out_size;                 // 256
    int T = in_sizes[0] / B;          // 3000
    int grid = (B + 1) / 2;           // 128 CTAs -> 1 per SM

    gru_scan_kernel<<<grid, NTHREADS>>>(x, W_ih, W_hh, b_ih, b_hh, W_fc, b_fc,
                                        (float*)d_out, B, T);
}

// round 6
// speedup vs baseline: 1.7424x; 1.4005x over previous
#include <cuda_runtime.h>

#define HIDDEN   64
#define GROUP    128            // threads per batch element: (unit j, k-half)
#define NTHREADS 256            // 2 batch groups per CTA, 8 warps

// ---------- packed f32x2 helpers ----------
__device__ __forceinline__ unsigned long long ffma2(unsigned long long a,
                                                    unsigned long long b,
                                                    unsigned long long c) {
    unsigned long long d;
    asm("fma.rn.f32x2 %0, %1, %2, %3;" : "=l"(d) : "l"(a), "l"(b), "l"(c));
    return d;
}
__device__ __forceinline__ unsigned long long fadd2(unsigned long long a,
                                                    unsigned long long b) {
    unsigned long long d;
    asm("add.rn.f32x2 %0, %1, %2;" : "=l"(d) : "l"(a), "l"(b));
    return d;
}
__device__ __forceinline__ unsigned long long pack2(float lo, float hi) {
    unsigned long long r;
    asm("mov.b64 %0, {%1, %2};" : "=l"(r) : "f"(lo), "f"(hi));
    return r;
}
__device__ __forceinline__ float2 unpack2(unsigned long long v) {
    float2 r;
    asm("mov.b64 {%0, %1}, %2;" : "=f"(r.x), "=f"(r.y) : "l"(v));
    return r;
}
__device__ __forceinline__ float tanh_approx(float x) {    // 1 MUFU
    float r; asm("tanh.approx.f32 %0, %1;" : "=f"(r) : "f"(x)); return r;
}

// one named barrier per batch group per step
__device__ __forceinline__ void bar_group(int id) {
    asm volatile("bar.sync %0, %1;" :: "r"(id), "r"(GROUP) : "memory");
}

__global__ void __launch_bounds__(NTHREADS, 1)
gru_scan_kernel(const float* __restrict__ x,
                const float* __restrict__ W_ih,
                const float* __restrict__ W_hh,
                const float* __restrict__ b_ih,
                const float* __restrict__ b_hh,
                const float* __restrict__ W_fc,
                const float* __restrict__ b_fc,
                float* __restrict__ out,
                int Btotal, int T)
{
    __shared__ __align__(16) float h_sh[2][HIDDEN];   // [group][j]
    __shared__ float red_sh[2][4];

    const int tid  = threadIdx.x;
    const int m    = tid / GROUP;      // batch slot (warps 0-3 | 4-7)
    const int u    = tid % GROUP;
    const int wg   = u / 32;           // warp within group 0..3
    const int lane = u % 32;
    const int j    = wg * 16 + (lane & 15);   // hidden unit
    const int half = lane >> 4;               // k-half; partner = lane^16
    const int b    = blockIdx.x * 2 + m;

    // ---- all 3 gate half-rows in registers: 3 x 16 packed f32x2 ----
    unsigned long long wreg[3][16];
    #pragma unroll
    for (int g = 0; g < 3; g++) {
        const float4* row = reinterpret_cast<const float4*>(
            W_hh + (g * HIDDEN + j) * HIDDEN + half * 32);
        #pragma unroll
        for (int i = 0; i < 8; i++) {
            float4 v = row[i];
            wreg[g][2 * i]     = pack2(v.x, v.y);
            wreg[g][2 * i + 1] = pack2(v.z, v.w);
        }
    }

    // per-unit constants (pre-halved for the tanh-sigmoid identity)
    const float wr_h = 0.5f * W_ih[j];
    const float br_h = 0.5f * (b_ih[j] + b_hh[j]);
    const float wz_h = 0.5f * W_ih[HIDDEN + j];
    const float bz_h = 0.5f * (b_ih[HIDDEN + j] + b_hh[HIDDEN + j]);
    const float wn   = W_ih[2 * HIDDEN + j];
    const float bihn = b_ih[2 * HIDDEN + j];
    const float bhhn = b_hh[2 * HIDDEN + j];
    const float wfc  = W_fc[j];
    const float bfc  = __ldg(b_fc);

    const float* xb = x + (size_t)((b < Btotal) ? b : 0) * T;
    float xv = __ldg(xb);
    float h_old = 0.0f;

    if (half == 0) h_sh[m][j] = 0.0f;
    __syncthreads();

    const ulonglong2* h2 = reinterpret_cast<const ulonglong2*>(h_sh[m] + half * 32);
    const int barid = 1 + m;

    for (int t = 0; t < T; t++) {
        int tn = (t + 1 < T) ? t + 1 : T - 1;
        float xnext = __ldg(xb + tn);
        // x-terms (independent of h; overlap the LDS latency)
        float arh = fmaf(xv, wr_h, br_h);
        float azh = fmaf(xv, wz_h, bz_h);
        float ain = fmaf(xv, wn, bihn);

        // ---- load h half once (8 LDS.128 broadcast), reuse for 3 gates ----
        unsigned long long hreg[16];
        #pragma unroll
        for (int i = 0; i < 8; i++) {
            ulonglong2 v = h2[i];
            hreg[2 * i]     = v.x;
            hreg[2 * i + 1] = v.y;
        }

        // ---- 3 half-dots: 16 FFMA2 each, 4 chains ----
        float dots[3];
        #pragma unroll
        for (int g = 0; g < 3; g++) {
            unsigned long long a0, a1, a2, a3;
            a0 = ffma2(wreg[g][0], hreg[0], 0ull);
            a1 = ffma2(wreg[g][1], hreg[1], 0ull);
            a2 = ffma2(wreg[g][2], hreg[2], 0ull);
            a3 = ffma2(wreg[g][3], hreg[3], 0ull);
            #pragma unroll
            for (int i = 1; i < 4; i++) {
                a0 = ffma2(wreg[g][4 * i],     hreg[4 * i],     a0);
                a1 = ffma2(wreg[g][4 * i + 1], hreg[4 * i + 1], a1);
                a2 = ffma2(wreg[g][4 * i + 2], hreg[4 * i + 2], a2);
                a3 = ffma2(wreg[g][4 * i + 3], hreg[4 * i + 3], a3);
            }
            unsigned long long s = fadd2(fadd2(a0, a1), fadd2(a2, a3));
            float2 sp = unpack2(s);
            dots[g] = sp.x + sp.y;
        }

        // ---- full dots via intra-warp half exchange (no barrier) ----
        float dr = dots[0] + __shfl_xor_sync(0xffffffffu, dots[0], 16);
        float dz = dots[1] + __shfl_xor_sync(0xffffffffu, dots[1], 16);
        float dn = dots[2] + __shfl_xor_sync(0xffffffffu, dots[2], 16);

        // ---- nonlinearity + update, fully local ----
        float tau_r = tanh_approx(fmaf(0.5f, dr, arh));   // sigmoid via tanh
        float tau_z = tanh_approx(fmaf(0.5f, dz, azh));
        float dnb   = dn + bhhn;
        float narg  = fmaf(tau_r, 0.5f * dnb, fmaf(0.5f, dnb, ain));
        float nval  = tanh_approx(narg);
        float d     = h_old - nval;                        // h = n + z*(h-n)
        h_old = fmaf(tau_z, 0.5f * d, fmaf(0.5f, d, nval));

        if (half == 0) h_sh[m][j] = h_old;   // both halves computed identical h
        bar_group(barid);                    // h published; drains the STS
        xv = xnext;
    }

    // ---- out[b] = h . W_fc + b_fc ----
    float v = (half == 0) ? h_old * wfc : 0.0f;
    #pragma unroll
    for (int o = 16; o > 0; o >>= 1)
        v += __shfl_xor_sync(0xffffffffu, v, o);
    if (lane == 0) red_sh[m][wg] = v;
    __syncthreads();
    if (u == 0 && b < Btotal) {
        out[b] = red_sh[m][0] + red_sh[m][1] + red_sh[m][2] + red_sh[m][3] + bfc;
    }
}

extern "C" void kernel_launch(void* const* d_in, const int* in_sizes, int n_in,
                              void* d_out, int out_size)
{
    const float* x    = (const float*)d_in[0];
    const float* W_ih = (const float*)d_in[1];
    const float* W_hh = (const float*)d_in[2];
    const float* b_ih = (const float*)d_in[3];
    const float* b_hh = (const float*)d_in[4];
    const float* W_fc = (const float*)d_in[5];
    const float* b_fc = (const float*)d_in[6];

    int B = out_size;                 // 256
    int T = in_sizes[0] / B;          // 3000
    int grid = (B + 1) / 2;           // 128 CTAs -> 1 per SM

    gru_scan_kernel<<<grid, NTHREADS>>>(x, W_ih, W_hh, b_ih, b_hh, W_fc, b_fc,
                                        (float*)d_out, B, T);
}